// round 5
// baseline (speedup 1.0000x reference)
#include <cuda_runtime.h>
#include <stdint.h>

// Problem constants (fixed shapes per reference)
constexpr int D      = 256;    // IN_CHANNELS
constexpr int NPER   = 100;    // nodes per graph
constexpr int KSEL   = 50;     // ceil(0.5 * 100)
constexpr int NGRAPH = 1000;   // 100000 / 100
constexpr int NPAD   = 128;    // bitonic padding

// out layout (float32, 150000 elems):
//   [0      , 50000)  node_index  (as float)
//   [50000  , 100000) cluster_index (= arange)
//   [100000 , 150000) weight (scores of selected nodes)

__global__ __launch_bounds__(256) void selectsparse_kernel(
    const float* __restrict__ x,
    const float* __restrict__ W,
    const float* __restrict__ b,
    float* __restrict__ out)
{
    __shared__ float s_scores[NPER];
    __shared__ unsigned long long s_keys[NPAD];

    const int g    = blockIdx.x;
    const int tid  = threadIdx.x;
    const int lane = tid & 31;
    const int warp = tid >> 5;

    // Each lane holds its 8-float slice of W in registers (W is tiny, L2-hot).
    const float4 w0 = reinterpret_cast<const float4*>(W)[lane * 2 + 0];
    const float4 w1 = reinterpret_cast<const float4*>(W)[lane * 2 + 1];
    const float bias = b[0];

    const float4* xg = reinterpret_cast<const float4*>(x + (size_t)g * NPER * D);

    // Warp w handles node pair {2w, 2w+1}, then strides by 16.
    // Pairs tile [0,16)+16t -> every node in [0,100) covered exactly once.
    // 4 independent LDG.128 per lane are issued before any consumption (MLP).
    for (int n = warp * 2; n < NPER; n += 16) {
        const int n2 = n + 1;
        const float4* rowA = xg + n * (D / 4);
        float4 a0 = rowA[lane * 2 + 0];
        float4 a1 = rowA[lane * 2 + 1];
        float4 b0, b1;
        const bool has2 = (n2 < NPER);
        if (has2) {
            const float4* rowB = xg + n2 * (D / 4);
            b0 = rowB[lane * 2 + 0];
            b1 = rowB[lane * 2 + 1];
        }
        float sA = a0.x * w0.x + a0.y * w0.y + a0.z * w0.z + a0.w * w0.w
                 + a1.x * w1.x + a1.y * w1.y + a1.z * w1.z + a1.w * w1.w;
        float sB = 0.0f;
        if (has2) {
            sB = b0.x * w0.x + b0.y * w0.y + b0.z * w0.z + b0.w * w0.w
               + b1.x * w1.x + b1.y * w1.y + b1.z * w1.z + b1.w * w1.w;
        }
        #pragma unroll
        for (int o = 16; o > 0; o >>= 1) {
            sA += __shfl_xor_sync(0xffffffffu, sA, o);
            sB += __shfl_xor_sync(0xffffffffu, sB, o);
        }
        if (lane == 0) {
            s_scores[n] = sA + bias;
            if (has2) s_scores[n2] = sB + bias;
        }
    }
    __syncthreads();

    // Pack sortable keys: high 32 = order-preserving float bits (descending),
    // low 32 = ~local_index (ties break toward smaller index, matching lax.top_k).
    if (tid < NPAD) {
        unsigned long long key = 0ull;  // padding sorts last (real keys are > 0)
        if (tid < NPER) {
            unsigned int u   = __float_as_uint(s_scores[tid]);
            unsigned int ord = (u & 0x80000000u) ? ~u : (u | 0x80000000u);
            key = ((unsigned long long)ord << 32) | (unsigned int)(~tid);
        }
        s_keys[tid] = key;
    }
    __syncthreads();

    // Bitonic sort, 128 elements, overall DESCENDING. 64 comparators per phase.
    #pragma unroll 1
    for (int k = 2; k <= NPAD; k <<= 1) {
        #pragma unroll 1
        for (int j = k >> 1; j > 0; j >>= 1) {
            if (tid < NPAD / 2) {
                int idx = ((tid & ~(j - 1)) << 1) | (tid & (j - 1));
                int p   = idx | j;
                bool desc = ((idx & k) == 0);
                unsigned long long a = s_keys[idx];
                unsigned long long c = s_keys[p];
                bool do_swap = desc ? (a < c) : (a > c);
                if (do_swap) { s_keys[idx] = c; s_keys[p] = a; }
            }
            __syncthreads();
        }
    }

    // Emit top-50.
    if (tid < KSEL) {
        unsigned long long key = s_keys[tid];
        int local = (int)(~((unsigned int)key));
        int node  = g * NPER + local;
        int cl    = g * KSEL + tid;
        out[cl]                       = (float)node;
        out[NGRAPH * KSEL + cl]       = (float)cl;
        out[2 * NGRAPH * KSEL + cl]   = s_scores[local];
    }
}

extern "C" void kernel_launch(void* const* d_in, const int* in_sizes, int n_in,
                              void* d_out, int out_size) {
    // Identify inputs by element count (robust to metadata ordering):
    //   x: 100000*256 = 25,600,000 f32 | batch: 100,000 (unused) | W: 256 | b: 1
    const float* x = nullptr;
    const float* W = nullptr;
    const float* b = nullptr;
    for (int i = 0; i < n_in; i++) {
        if      (in_sizes[i] == NGRAPH * NPER * D) x = (const float*)d_in[i];
        else if (in_sizes[i] == D)                 W = (const float*)d_in[i];
        else if (in_sizes[i] == 1)                 b = (const float*)d_in[i];
    }
    // Fallback to positional order if counts didn't match.
    if (!x) x = (const float*)d_in[0];
    if (!W) W = (const float*)d_in[2];
    if (!b) b = (const float*)d_in[3];
    (void)out_size;
    selectsparse_kernel<<<NGRAPH, 256>>>(x, W, b, (float*)d_out);
}

// round 6
// speedup vs baseline: 1.3439x; 1.3439x over previous
#include <cuda_runtime.h>
#include <stdint.h>

// Problem constants (fixed shapes per reference)
constexpr int D      = 256;    // IN_CHANNELS
constexpr int NPER   = 100;    // nodes per graph
constexpr int KSEL   = 50;     // ceil(0.5 * 100)
constexpr int NGRAPH = 1000;   // 100000 / 100

// out layout (float32, 150000 elems):
//   [0      , 50000)  node_index  (as float)
//   [50000  , 100000) cluster_index (= arange)
//   [100000 , 150000) weight (scores of selected nodes)

__global__ __launch_bounds__(256) void selectsparse_kernel(
    const float* __restrict__ x,
    const float* __restrict__ W,
    const float* __restrict__ b,
    float* __restrict__ out)
{
    __shared__ float s_scores[NPER];

    const int g    = blockIdx.x;
    const int tid  = threadIdx.x;
    const int lane = tid & 31;
    const int warp = tid >> 5;

    // Each lane holds its 8-float slice of W in registers (tiny, L2-hot).
    const float4 w0 = reinterpret_cast<const float4*>(W)[lane * 2 + 0];
    const float4 w1 = reinterpret_cast<const float4*>(W)[lane * 2 + 1];
    const float bias = b[0];

    const float4* xg = reinterpret_cast<const float4*>(x + (size_t)g * NPER * D);

    // Warp w handles node pair {2w, 2w+1}, striding by 16.
    // All 4 LDG.128 per lane issue before any FMA consumes them (MLP=4).
    for (int n = warp * 2; n < NPER; n += 16) {
        const int n2 = n + 1;
        const float4* rowA = xg + n * (D / 4);
        float4 a0 = rowA[lane * 2 + 0];
        float4 a1 = rowA[lane * 2 + 1];
        float4 b0, b1;
        const bool has2 = (n2 < NPER);
        if (has2) {
            const float4* rowB = xg + n2 * (D / 4);
            b0 = rowB[lane * 2 + 0];
            b1 = rowB[lane * 2 + 1];
        }
        float sA = a0.x * w0.x + a0.y * w0.y + a0.z * w0.z + a0.w * w0.w
                 + a1.x * w1.x + a1.y * w1.y + a1.z * w1.z + a1.w * w1.w;
        float sB = 0.0f;
        if (has2) {
            sB = b0.x * w0.x + b0.y * w0.y + b0.z * w0.z + b0.w * w0.w
               + b1.x * w1.x + b1.y * w1.y + b1.z * w1.z + b1.w * w1.w;
        }
        #pragma unroll
        for (int o = 16; o > 0; o >>= 1) {
            sA += __shfl_xor_sync(0xffffffffu, sA, o);
            sB += __shfl_xor_sync(0xffffffffu, sB, o);
        }
        if (lane == 0) {
            s_scores[n] = sA + bias;
            if (has2) s_scores[n2] = sB + bias;
        }
    }
    __syncthreads();   // the ONLY barrier

    // Rank selection: scores are distinct in practice, and the (j < t)
    // tie-break makes ranks unique regardless — identical ordering to
    // lax.top_k (descending, stable). Thread t owns node t; its rank is
    // the number of nodes ordered before it. rank < 50 -> emit at slot rank.
    if (tid < NPER) {
        const float st = s_scores[tid];
        int r = 0;
        #pragma unroll 4
        for (int j = 0; j < NPER; j++) {
            const float sj = s_scores[j];   // broadcast LDS, conflict-free
            r += (sj > st) | ((sj == st) & (j < tid));
        }
        if (r < KSEL) {
            const int node = g * NPER + tid;
            const int cl   = g * KSEL + r;
            out[cl]                     = (float)node;
            out[NGRAPH * KSEL + cl]     = (float)cl;
            out[2 * NGRAPH * KSEL + cl] = st;
        }
    }
}

extern "C" void kernel_launch(void* const* d_in, const int* in_sizes, int n_in,
                              void* d_out, int out_size) {
    // Identify inputs by element count (robust to metadata ordering):
    //   x: 25,600,000 f32 | batch: 100,000 (unused) | W: 256 | b: 1
    const float* x = nullptr;
    const float* W = nullptr;
    const float* b = nullptr;
    for (int i = 0; i < n_in; i++) {
        if      (in_sizes[i] == NGRAPH * NPER * D) x = (const float*)d_in[i];
        else if (in_sizes[i] == D)                 W = (const float*)d_in[i];
        else if (in_sizes[i] == 1)                 b = (const float*)d_in[i];
    }
    if (!x) x = (const float*)d_in[0];
    if (!W) W = (const float*)d_in[2];
    if (!b) b = (const float*)d_in[3];
    (void)out_size;
    selectsparse_kernel<<<NGRAPH, 256>>>(x, W, b, (float*)d_out);
}